// round 13
// baseline (speedup 1.0000x reference)
#include <cuda_runtime.h>
#include <cuda_bf16.h>
#include <cuda_fp16.h>
#include <cstdint>

// Problem constants
#define BB 8
#define TT 20
#define CIN 64
#define HID 64
#define HH 64
#define WW 64
#define HWSZ 4096          // 64*64
#define CC 128             // CIN + HID
#define C4 256             // 4*HID
#define EPSBN 1e-5f

typedef unsigned long long ull;

// -------- persistent device state --------
__device__ float g_h0[BB * HID * HWSZ];         // zero h for t=0
__device__ float g_c[BB * HID * HWSZ];
__device__ uint32_t g_d16[BB * CC * HWSZ / 2];  // fp16x2 selu(bn1(dw(z))), [b][k][px/2]
__device__ unsigned short g_wh[32768];          // fp16 W [r][k], swizzled (64KB)
__device__ float g_sp[256];                     // bn2 shift, [j*4+gate]
__device__ float g_dwf[CC * 9];
__device__ float g_dwb[CC];

// -------- helpers --------
__device__ __forceinline__ uint32_t smem_u32(const void* p) {
    uint32_t a;
    asm("{ .reg .u64 t; cvta.to.shared.u64 t, %1; cvt.u32.u64 %0, t; }" : "=r"(a) : "l"(p));
    return a;
}
__device__ __forceinline__ void ldm4(uint32_t* r, uint32_t a) {
    asm volatile("ldmatrix.sync.aligned.m8n8.x4.shared.b16 {%0,%1,%2,%3}, [%4];"
        : "=r"(r[0]), "=r"(r[1]), "=r"(r[2]), "=r"(r[3]) : "r"(a));
}
__device__ __forceinline__ void mma_f16(float* d, const uint32_t* a, uint32_t b0, uint32_t b1) {
    asm volatile("mma.sync.aligned.m16n8k16.row.col.f32.f16.f16.f32 "
        "{%0,%1,%2,%3}, {%4,%5,%6,%7}, {%8,%9}, {%0,%1,%2,%3};"
        : "+f"(d[0]), "+f"(d[1]), "+f"(d[2]), "+f"(d[3])
        : "r"(a[0]), "r"(a[1]), "r"(a[2]), "r"(a[3]), "r"(b0), "r"(b1));
}
__device__ __forceinline__ uint32_t prmt(uint32_t a, uint32_t b, uint32_t sel) {
    uint32_t r;
    asm("prmt.b32 %0, %1, %2, %3;" : "=r"(r) : "r"(a), "r"(b), "r"(sel));
    return r;
}
__device__ __forceinline__ float tanha(float x) {
    float r;
    asm("tanh.approx.f32 %0, %1;" : "=f"(r) : "f"(x));
    return r;
}
__device__ __forceinline__ float selu_f(float x) {
    const float s = 1.0507009873554805f;
    const float sa = 1.7580993408473766f;
    return x > 0.f ? s * x : sa * (__expf(x) - 1.f);
}
__device__ __forceinline__ float gate_f(float x) {       // exact: i, f, g
    float u = selu_f(x);
    return __fdividef(1.f, 1.f + __expf(-u));
}
__device__ __forceinline__ float gate_fast(float x) {    // o gate
    float u = selu_f(x);
    return 0.5f + 0.5f * tanha(0.5f * u);
}

// -------- init --------
__global__ void init_kernel() {
    int i = blockIdx.x * blockDim.x + threadIdx.x;
    if (i < BB * HID * HWSZ) { g_h0[i] = 0.f; g_c[i] = 0.f; }
}

// -------- prep --------
__global__ void prep_kernel(const float* __restrict__ dw_w,
                            const float* __restrict__ g1, const float* __restrict__ b1,
                            const float* __restrict__ m1, const float* __restrict__ v1,
                            const float* __restrict__ pw,
                            const float* __restrict__ g2, const float* __restrict__ b2,
                            const float* __restrict__ m2, const float* __restrict__ v2) {
    int tid = threadIdx.x;   // 256
    if (tid < CC) {
        float s = g1[tid] * rsqrtf(v1[tid] + EPSBN);
        #pragma unroll
        for (int k = 0; k < 9; k++) g_dwf[tid * 9 + k] = dw_w[tid * 9 + k] * s;
        g_dwb[tid] = b1[tid] - m1[tid] * s;
    }
    {
        int oc = tid;
        float s = g2[oc] * rsqrtf(v2[oc] + EPSBN);
        int gate = oc >> 6;
        int j = oc & 63;
        int r = j * 4 + gate;
        g_sp[r] = b2[oc] - m2[oc] * s;
        for (int k = 0; k < 128; k++) {
            float wv = pw[oc * 128 + k] * s;
            __half hw = __float2half(wv);
            uint32_t off = (uint32_t)r * 256 + (uint32_t)(((k >> 3) ^ (r & 7)) * 16) + (k & 7) * 2;
            g_wh[off >> 1] = *(unsigned short*)&hw;
        }
    }
}

// -------- depthwise 3x3 + BN1 + SELU -> fp16x2 --------
__global__ void dw_kernel(const float* __restrict__ x, const float* __restrict__ hprev, int t) {
    int idx = blockIdx.x * blockDim.x + threadIdx.x;   // 1,048,576 threads, 4 px each
    int w4 = idx & 15;
    int y  = (idx >> 4) & 63;
    int c  = (idx >> 10) & 127;
    int b  = idx >> 17;
    int x0 = w4 << 2;

    const float* src = (c < CIN)
        ? x + ((size_t)(b * TT + t) * CIN + c) * HWSZ
        : hprev + ((size_t)b * (size_t)(t == 0 ? HID : TT * HID) + (size_t)(t == 0 ? 0 : (t - 1) * HID) + (c - CIN)) * HWSZ;

    float r0[6], r1[6], r2[6];
    int ybase = y * WW;
    bool yt = (y > 0), yb = (y < HH - 1);
    #pragma unroll
    for (int dx = 0; dx < 6; dx++) {
        int xx = x0 - 1 + dx;
        bool xv = (xx >= 0) && (xx < WW);
        r0[dx] = (yt && xv) ? __ldg(src + ybase - WW + xx) : 0.f;
        r1[dx] = xv ? __ldg(src + ybase + xx) : 0.f;
        r2[dx] = (yb && xv) ? __ldg(src + ybase + WW + xx) : 0.f;
    }
    float w[9];
    #pragma unroll
    for (int i = 0; i < 9; i++) w[i] = __ldg(g_dwf + c * 9 + i);
    float bias = __ldg(g_dwb + c);

    float o[4];
    #pragma unroll
    for (int p = 0; p < 4; p++) {
        float acc = bias;
        acc += w[0]*r0[p] + w[1]*r0[p+1] + w[2]*r0[p+2];
        acc += w[3]*r1[p] + w[4]*r1[p+1] + w[5]*r1[p+2];
        acc += w[6]*r2[p] + w[7]*r2[p+1] + w[8]*r2[p+2];
        o[p] = selu_f(acc);
    }
    uint2 v;
    asm("cvt.rn.f16x2.f32 %0, %1, %2;" : "=r"(v.x) : "f"(o[1]), "f"(o[0]));
    asm("cvt.rn.f16x2.f32 %0, %1, %2;" : "=r"(v.y) : "f"(o[3]), "f"(o[2]));
    *(uint2*)(g_d16 + (((size_t)(b * CC + c) * HWSZ + ybase + x0) >> 1)) = v;
}

// -------- fp16 HMMA pointwise GEMM + LSTM epilogue --------
// 296 CTAs x 256 threads, 2 CTAs/SM for cross-CTA phase overlap.
// Tile = (b, 64 px) x 256 oc x 128 k; 512 tiles; CTA does tiles bid, bid+296.
// smem: W fp16 [0,64K), A fp16 [64K,80K) (64 rows x 256B).
__global__ void __launch_bounds__(256, 2)
pw_kernel(float* __restrict__ out, int t) {
    extern __shared__ char smem[];
    uint32_t sb = smem_u32(smem);
    int tid = threadIdx.x;
    int w = tid >> 5, lane = tid & 31;
    int pb = w & 1, ob = w >> 1;           // warp-tile: 32px x 64oc

    // stage W once (64 KB)
    {
        const float4* src = (const float4*)g_wh;
        float4* dst = (float4*)smem;
        #pragma unroll
        for (int i = 0; i < 16; i++) dst[tid + i * 256] = src[tid + i * 256];
    }

    // preload BN2 shifts
    float2 spr[8];
    #pragma unroll
    for (int nt = 0; nt < 8; nt++)
        spr[nt] = __ldg((const float2*)(g_sp + ob * 64 + nt * 8 + 2 * (lane & 3)));

    const uint32_t ABASE = sb + 65536;
    int arow = pb * 32 + (lane & 15);
    int apar = (lane >> 4) & 1;
    int asw  = arow & 7;
    int wrow = ob * 64 + (lane & 7) + (((lane >> 4) & 1) << 3);
    int wpar = (lane >> 3) & 1;
    int wsw  = wrow & 7;

    // A-build mapping: warp w owns kq = w (k-range w*16..w*16+15), lanes = px-pairs
    int kq = w;            // 0..7
    int p2 = lane;         // 0..31 -> px pair (2*p2, 2*p2+1)
    int px0 = 2 * p2, px1 = px0 + 1;
    uint32_t stq[2][2];    // [px][q] STS addresses
    #pragma unroll
    for (int q = 0; q < 2; q++) {
        stq[0][q] = 65536u + (uint32_t)px0 * 256 + (uint32_t)(((kq << 1) + q) ^ (px0 & 7)) * 16;
        stq[1][q] = 65536u + (uint32_t)px1 * 256 + (uint32_t)(((kq << 1) + q) ^ (px1 & 7)) * 16;
    }

    // prologue: build A for first tile
    {
        int tile = blockIdx.x;
        int b  = tile >> 6;
        int p0 = (tile & 63) << 6;
        const uint32_t* src = g_d16 + (((size_t)(b * CC + kq * 16) * HWSZ) >> 1) + (p0 >> 1) + p2;
        uint32_t u[16];
        #pragma unroll
        for (int i = 0; i < 16; i++) u[i] = __ldg(src + i * (HWSZ / 2));
        #pragma unroll
        for (int q = 0; q < 2; q++) {
            uint4 v0, v1;
            uint32_t* v0p = &v0.x; uint32_t* v1p = &v1.x;
            #pragma unroll
            for (int jj = 0; jj < 4; jj++) {
                int j = q * 4 + jj;
                v0p[jj] = prmt(u[2*j], u[2*j+1], 0x5410);
                v1p[jj] = prmt(u[2*j], u[2*j+1], 0x7632);
            }
            *(uint4*)(smem + stq[0][q]) = v0;
            *(uint4*)(smem + stq[1][q]) = v1;
        }
    }
    __syncthreads();

    for (int tile = blockIdx.x; tile < 512; tile += 296) {
        int b  = tile >> 6;
        int p0 = (tile & 63) << 6;
        int ntile = tile + 296;
        bool hasNext = ntile < 512;
        int nb  = ntile >> 6;
        int np0 = (ntile & 63) << 6;

        // ---- MMA mainloop ----
        float acc[2][8][4];
        #pragma unroll
        for (int mt = 0; mt < 2; mt++)
            #pragma unroll
            for (int nt = 0; nt < 8; nt++)
                #pragma unroll
                for (int q = 0; q < 4; q++) acc[mt][nt][q] = 0.f;

        #pragma unroll
        for (int kc = 0; kc < 8; kc++) {
            uint32_t ah[2][4];
            uint32_t chunkA = (uint32_t)((2 * kc + apar) ^ asw) * 16;
            ldm4(ah[0], ABASE + (uint32_t)arow * 256 + chunkA);
            ldm4(ah[1], ABASE + (uint32_t)(arow + 16) * 256 + chunkA);
            #pragma unroll
            for (int np = 0; np < 4; np++) {
                uint32_t chunk = (uint32_t)((2 * kc + wpar) ^ wsw);
                uint32_t addr = sb + (uint32_t)(wrow + np * 16) * 256 + chunk * 16;
                uint32_t wf[4];
                ldm4(wf, addr);
                #pragma unroll
                for (int mt = 0; mt < 2; mt++) {
                    mma_f16(acc[mt][np*2],   ah[mt], wf[0], wf[1]);
                    mma_f16(acc[mt][np*2+1], ah[mt], wf[2], wf[3]);
                }
            }
        }
        __syncthreads();

        // ---- prefetch next tile's A (latency hidden under epilogue) ----
        uint32_t u[16];
        if (hasNext) {
            const uint32_t* src = g_d16 + (((size_t)(nb * CC + kq * 16) * HWSZ) >> 1) + (np0 >> 1) + p2;
            #pragma unroll
            for (int i = 0; i < 16; i++) u[i] = __ldg(src + i * (HWSZ / 2));
        }

        // ---- epilogue ----
        int odd = lane & 1;
        #pragma unroll
        for (int uu = 0; uu < 16; uu++) {
            int mt = uu >> 3, nt = uu & 7;
            float* a = acc[mt][nt];
            float2 sp = spr[nt];
            float v0 = a[0] + sp.x, v1 = a[1] + sp.y;
            float v2 = a[2] + sp.x, v3 = a[3] + sp.y;
            float sx = odd ? v0 : v2;
            float sy = odd ? v1 : v3;
            float ex = __shfl_xor_sync(0xFFFFFFFFu, sx, 1);
            float ey = __shfl_xor_sync(0xFFFFFFFFu, sy, 1);
            float zi, zf, zo, zg; int rr;
            if (!odd) { zi = v0; zf = v1; zo = ex; zg = ey; rr = lane >> 2; }
            else      { zi = ex; zf = ey; zo = v2; zg = v3; rr = (lane >> 2) + 8; }
            int j   = ob * 16 + nt * 2 + ((lane >> 1) & 1);
            int ppx = pb * 32 + mt * 16 + rr;
            size_t plane = ((size_t)b * HID + j) * HWSZ + p0 + ppx;
            float co = __ldg(g_c + plane);
            float gi = gate_f(zi);
            float gf = gate_f(zf);
            float gg = gate_f(zg);
            float go = gate_fast(zo);
            float cv = gf * co + gi * gg;
            float hv = go * tanha(cv);
            g_c[plane] = cv;
            out[((size_t)(b * TT + t) * HID + j) * HWSZ + p0 + ppx] = hv;
        }

        // ---- store next tile's A ----
        if (hasNext) {
            #pragma unroll
            for (int q = 0; q < 2; q++) {
                uint4 v0, v1;
                uint32_t* v0p = &v0.x; uint32_t* v1p = &v1.x;
                #pragma unroll
                for (int jj = 0; jj < 4; jj++) {
                    int j = q * 4 + jj;
                    v0p[jj] = prmt(u[2*j], u[2*j+1], 0x5410);
                    v1p[jj] = prmt(u[2*j], u[2*j+1], 0x7632);
                }
                *(uint4*)(smem + stq[0][q]) = v0;
                *(uint4*)(smem + stq[1][q]) = v1;
            }
        }
        __syncthreads();
    }
}

// -------- launch --------
extern "C" void kernel_launch(void* const* d_in, const int* in_sizes, int n_in,
                              void* d_out, int out_size) {
    const float* x      = (const float*)d_in[0];
    const float* dw_w   = (const float*)d_in[1];
    const float* gamma1 = (const float*)d_in[2];
    const float* beta1  = (const float*)d_in[3];
    const float* mean1  = (const float*)d_in[4];
    const float* var1   = (const float*)d_in[5];
    const float* pw_w   = (const float*)d_in[6];
    const float* gamma2 = (const float*)d_in[7];
    const float* beta2  = (const float*)d_in[8];
    const float* mean2  = (const float*)d_in[9];
    const float* var2   = (const float*)d_in[10];
    float* out = (float*)d_out;

    cudaFuncSetAttribute(pw_kernel, cudaFuncAttributeMaxDynamicSharedMemorySize, 81920);

    init_kernel<<<(BB * HID * HWSZ + 511) / 512, 512>>>();
    prep_kernel<<<1, 256>>>(dw_w, gamma1, beta1, mean1, var1,
                            pw_w, gamma2, beta2, mean2, var2);

    for (int t = 0; t < TT; t++) {
        const float* hprev = (t == 0) ? (const float*)g_h0 : (const float*)out;
        dw_kernel<<<4096, 256>>>(x, hprev, t);
        pw_kernel<<<296, 256, 81920>>>(out, t);
    }
}

// round 14
// speedup vs baseline: 1.0040x; 1.0040x over previous
#include <cuda_runtime.h>
#include <cuda_bf16.h>
#include <cuda_fp16.h>
#include <cstdint>

// Problem constants
#define BB 8
#define TT 20
#define CIN 64
#define HID 64
#define HH 64
#define WW 64
#define HWSZ 4096          // 64*64
#define CC 128             // CIN + HID
#define C4 256             // 4*HID
#define EPSBN 1e-5f

typedef unsigned long long ull;

// -------- persistent device state --------
__device__ float g_h0[BB * HID * HWSZ];         // zero h for t=0
__device__ float g_c[BB * HID * HWSZ];
__device__ uint32_t g_d16[BB * CC * HWSZ / 2];  // fp16x2 selu(bn1(dw(z))), [b][k][px/2]
__device__ unsigned short g_wh[32768];          // fp16 W [r][k], swizzled (64KB)
__device__ float g_sp[256];                     // bn2 shift, [j*4+gate]
__device__ float g_dwf[CC * 9];
__device__ float g_dwb[CC];

// -------- helpers --------
__device__ __forceinline__ uint32_t smem_u32(const void* p) {
    uint32_t a;
    asm("{ .reg .u64 t; cvta.to.shared.u64 t, %1; cvt.u32.u64 %0, t; }" : "=r"(a) : "l"(p));
    return a;
}
__device__ __forceinline__ void ldm4(uint32_t* r, uint32_t a) {
    asm volatile("ldmatrix.sync.aligned.m8n8.x4.shared.b16 {%0,%1,%2,%3}, [%4];"
        : "=r"(r[0]), "=r"(r[1]), "=r"(r[2]), "=r"(r[3]) : "r"(a));
}
__device__ __forceinline__ void mma_f16(float* d, const uint32_t* a, uint32_t b0, uint32_t b1) {
    asm volatile("mma.sync.aligned.m16n8k16.row.col.f32.f16.f16.f32 "
        "{%0,%1,%2,%3}, {%4,%5,%6,%7}, {%8,%9}, {%0,%1,%2,%3};"
        : "+f"(d[0]), "+f"(d[1]), "+f"(d[2]), "+f"(d[3])
        : "r"(a[0]), "r"(a[1]), "r"(a[2]), "r"(a[3]), "r"(b0), "r"(b1));
}
__device__ __forceinline__ uint32_t prmt(uint32_t a, uint32_t b, uint32_t sel) {
    uint32_t r;
    asm("prmt.b32 %0, %1, %2, %3;" : "=r"(r) : "r"(a), "r"(b), "r"(sel));
    return r;
}
__device__ __forceinline__ float tanha(float x) {
    float r;
    asm("tanh.approx.f32 %0, %1;" : "=f"(r) : "f"(x));
    return r;
}
__device__ __forceinline__ float selu_f(float x) {
    const float s = 1.0507009873554805f;
    const float sa = 1.7580993408473766f;
    return x > 0.f ? s * x : sa * (__expf(x) - 1.f);
}
__device__ __forceinline__ float gate_f(float x) {       // exact: i, f, g
    float u = selu_f(x);
    return __fdividef(1.f, 1.f + __expf(-u));
}
__device__ __forceinline__ float gate_fast(float x) {    // o gate
    float u = selu_f(x);
    return 0.5f + 0.5f * tanha(0.5f * u);
}

// -------- init --------
__global__ void init_kernel() {
    int i = blockIdx.x * blockDim.x + threadIdx.x;
    if (i < BB * HID * HWSZ) { g_h0[i] = 0.f; g_c[i] = 0.f; }
}

// -------- prep --------
__global__ void prep_kernel(const float* __restrict__ dw_w,
                            const float* __restrict__ g1, const float* __restrict__ b1,
                            const float* __restrict__ m1, const float* __restrict__ v1,
                            const float* __restrict__ pw,
                            const float* __restrict__ g2, const float* __restrict__ b2,
                            const float* __restrict__ m2, const float* __restrict__ v2) {
    int tid = threadIdx.x;   // 256
    if (tid < CC) {
        float s = g1[tid] * rsqrtf(v1[tid] + EPSBN);
        #pragma unroll
        for (int k = 0; k < 9; k++) g_dwf[tid * 9 + k] = dw_w[tid * 9 + k] * s;
        g_dwb[tid] = b1[tid] - m1[tid] * s;
    }
    {
        int oc = tid;
        float s = g2[oc] * rsqrtf(v2[oc] + EPSBN);
        int gate = oc >> 6;
        int j = oc & 63;
        int r = j * 4 + gate;
        g_sp[r] = b2[oc] - m2[oc] * s;
        for (int k = 0; k < 128; k++) {
            float wv = pw[oc * 128 + k] * s;
            __half hw = __float2half(wv);
            uint32_t off = (uint32_t)r * 256 + (uint32_t)(((k >> 3) ^ (r & 7)) * 16) + (k & 7) * 2;
            g_wh[off >> 1] = *(unsigned short*)&hw;
        }
    }
}

// -------- depthwise 3x3 + BN1 + SELU -> fp16x2 --------
__global__ void dw_kernel(const float* __restrict__ x, const float* __restrict__ hprev, int t) {
    int idx = blockIdx.x * blockDim.x + threadIdx.x;   // 1,048,576 threads, 4 px each
    int w4 = idx & 15;
    int y  = (idx >> 4) & 63;
    int c  = (idx >> 10) & 127;
    int b  = idx >> 17;
    int x0 = w4 << 2;

    const float* src = (c < CIN)
        ? x + ((size_t)(b * TT + t) * CIN + c) * HWSZ
        : hprev + ((size_t)b * (size_t)(t == 0 ? HID : TT * HID) + (size_t)(t == 0 ? 0 : (t - 1) * HID) + (c - CIN)) * HWSZ;

    float r0[6], r1[6], r2[6];
    int ybase = y * WW;
    bool yt = (y > 0), yb = (y < HH - 1);
    #pragma unroll
    for (int dx = 0; dx < 6; dx++) {
        int xx = x0 - 1 + dx;
        bool xv = (xx >= 0) && (xx < WW);
        r0[dx] = (yt && xv) ? __ldg(src + ybase - WW + xx) : 0.f;
        r1[dx] = xv ? __ldg(src + ybase + xx) : 0.f;
        r2[dx] = (yb && xv) ? __ldg(src + ybase + WW + xx) : 0.f;
    }
    float w[9];
    #pragma unroll
    for (int i = 0; i < 9; i++) w[i] = __ldg(g_dwf + c * 9 + i);
    float bias = __ldg(g_dwb + c);

    float o[4];
    #pragma unroll
    for (int p = 0; p < 4; p++) {
        float acc = bias;
        acc += w[0]*r0[p] + w[1]*r0[p+1] + w[2]*r0[p+2];
        acc += w[3]*r1[p] + w[4]*r1[p+1] + w[5]*r1[p+2];
        acc += w[6]*r2[p] + w[7]*r2[p+1] + w[8]*r2[p+2];
        o[p] = selu_f(acc);
    }
    uint2 v;
    asm("cvt.rn.f16x2.f32 %0, %1, %2;" : "=r"(v.x) : "f"(o[1]), "f"(o[0]));
    asm("cvt.rn.f16x2.f32 %0, %1, %2;" : "=r"(v.y) : "f"(o[3]), "f"(o[2]));
    *(uint2*)(g_d16 + (((size_t)(b * CC + c) * HWSZ + ybase + x0) >> 1)) = v;
}

// -------- fp16 HMMA pointwise GEMM + LSTM epilogue --------
// 296 CTAs x 256 threads, 2 CTAs/SM for cross-CTA phase overlap.
// Tile = (b, 64 px) x 256 oc x 128 k; 512 tiles; CTA does tiles bid, bid+296.
// smem: W fp16 [0,64K), A fp16 [64K,80K) (64 rows x 256B).
__global__ void __launch_bounds__(256, 2)
pw_kernel(float* __restrict__ out, int t) {
    extern __shared__ char smem[];
    uint32_t sb = smem_u32(smem);
    int tid = threadIdx.x;
    int w = tid >> 5, lane = tid & 31;
    int pb = w & 1, ob = w >> 1;           // warp-tile: 32px x 64oc

    // stage W once (64 KB)
    {
        const float4* src = (const float4*)g_wh;
        float4* dst = (float4*)smem;
        #pragma unroll
        for (int i = 0; i < 16; i++) dst[tid + i * 256] = src[tid + i * 256];
    }

    // preload BN2 shifts
    float2 spr[8];
    #pragma unroll
    for (int nt = 0; nt < 8; nt++)
        spr[nt] = __ldg((const float2*)(g_sp + ob * 64 + nt * 8 + 2 * (lane & 3)));

    const uint32_t ABASE = sb + 65536;
    int arow = pb * 32 + (lane & 15);
    int apar = (lane >> 4) & 1;
    int asw  = arow & 7;
    int wrow = ob * 64 + (lane & 7) + (((lane >> 4) & 1) << 3);
    int wpar = (lane >> 3) & 1;
    int wsw  = wrow & 7;

    // A-build mapping: warp w owns kq = w (k-range w*16..w*16+15), lanes = px-pairs
    int kq = w;            // 0..7
    int p2 = lane;         // 0..31 -> px pair (2*p2, 2*p2+1)
    int px0 = 2 * p2, px1 = px0 + 1;
    uint32_t stq[2][2];    // [px][q] STS addresses
    #pragma unroll
    for (int q = 0; q < 2; q++) {
        stq[0][q] = 65536u + (uint32_t)px0 * 256 + (uint32_t)(((kq << 1) + q) ^ (px0 & 7)) * 16;
        stq[1][q] = 65536u + (uint32_t)px1 * 256 + (uint32_t)(((kq << 1) + q) ^ (px1 & 7)) * 16;
    }

    // prologue: build A for first tile
    {
        int tile = blockIdx.x;
        int b  = tile >> 6;
        int p0 = (tile & 63) << 6;
        const uint32_t* src = g_d16 + (((size_t)(b * CC + kq * 16) * HWSZ) >> 1) + (p0 >> 1) + p2;
        uint32_t u[16];
        #pragma unroll
        for (int i = 0; i < 16; i++) u[i] = __ldg(src + i * (HWSZ / 2));
        #pragma unroll
        for (int q = 0; q < 2; q++) {
            uint4 v0, v1;
            uint32_t* v0p = &v0.x; uint32_t* v1p = &v1.x;
            #pragma unroll
            for (int jj = 0; jj < 4; jj++) {
                int j = q * 4 + jj;
                v0p[jj] = prmt(u[2*j], u[2*j+1], 0x5410);
                v1p[jj] = prmt(u[2*j], u[2*j+1], 0x7632);
            }
            *(uint4*)(smem + stq[0][q]) = v0;
            *(uint4*)(smem + stq[1][q]) = v1;
        }
    }
    __syncthreads();

    for (int tile = blockIdx.x; tile < 512; tile += 296) {
        int b  = tile >> 6;
        int p0 = (tile & 63) << 6;
        int ntile = tile + 296;
        bool hasNext = ntile < 512;
        int nb  = ntile >> 6;
        int np0 = (ntile & 63) << 6;

        // ---- MMA mainloop ----
        float acc[2][8][4];
        #pragma unroll
        for (int mt = 0; mt < 2; mt++)
            #pragma unroll
            for (int nt = 0; nt < 8; nt++)
                #pragma unroll
                for (int q = 0; q < 4; q++) acc[mt][nt][q] = 0.f;

        #pragma unroll
        for (int kc = 0; kc < 8; kc++) {
            uint32_t ah[2][4];
            uint32_t chunkA = (uint32_t)((2 * kc + apar) ^ asw) * 16;
            ldm4(ah[0], ABASE + (uint32_t)arow * 256 + chunkA);
            ldm4(ah[1], ABASE + (uint32_t)(arow + 16) * 256 + chunkA);
            #pragma unroll
            for (int np = 0; np < 4; np++) {
                uint32_t chunk = (uint32_t)((2 * kc + wpar) ^ wsw);
                uint32_t addr = sb + (uint32_t)(wrow + np * 16) * 256 + chunk * 16;
                uint32_t wf[4];
                ldm4(wf, addr);
                #pragma unroll
                for (int mt = 0; mt < 2; mt++) {
                    mma_f16(acc[mt][np*2],   ah[mt], wf[0], wf[1]);
                    mma_f16(acc[mt][np*2+1], ah[mt], wf[2], wf[3]);
                }
            }
        }
        __syncthreads();

        // ---- prefetch next tile's A (latency hidden under epilogue) ----
        uint32_t u[16];
        if (hasNext) {
            const uint32_t* src = g_d16 + (((size_t)(nb * CC + kq * 16) * HWSZ) >> 1) + (np0 >> 1) + p2;
            #pragma unroll
            for (int i = 0; i < 16; i++) u[i] = __ldg(src + i * (HWSZ / 2));
        }

        // ---- epilogue ----
        int odd = lane & 1;
        #pragma unroll
        for (int uu = 0; uu < 16; uu++) {
            int mt = uu >> 3, nt = uu & 7;
            float* a = acc[mt][nt];
            float2 sp = spr[nt];
            float v0 = a[0] + sp.x, v1 = a[1] + sp.y;
            float v2 = a[2] + sp.x, v3 = a[3] + sp.y;
            float sx = odd ? v0 : v2;
            float sy = odd ? v1 : v3;
            float ex = __shfl_xor_sync(0xFFFFFFFFu, sx, 1);
            float ey = __shfl_xor_sync(0xFFFFFFFFu, sy, 1);
            float zi, zf, zo, zg; int rr;
            if (!odd) { zi = v0; zf = v1; zo = ex; zg = ey; rr = lane >> 2; }
            else      { zi = ex; zf = ey; zo = v2; zg = v3; rr = (lane >> 2) + 8; }
            int j   = ob * 16 + nt * 2 + ((lane >> 1) & 1);
            int ppx = pb * 32 + mt * 16 + rr;
            size_t plane = ((size_t)b * HID + j) * HWSZ + p0 + ppx;
            float co = __ldg(g_c + plane);
            float gi = gate_f(zi);
            float gf = gate_f(zf);
            float gg = gate_f(zg);
            float go = gate_fast(zo);
            float cv = gf * co + gi * gg;
            float hv = go * tanha(cv);
            g_c[plane] = cv;
            out[((size_t)(b * TT + t) * HID + j) * HWSZ + p0 + ppx] = hv;
        }

        // ---- store next tile's A ----
        if (hasNext) {
            #pragma unroll
            for (int q = 0; q < 2; q++) {
                uint4 v0, v1;
                uint32_t* v0p = &v0.x; uint32_t* v1p = &v1.x;
                #pragma unroll
                for (int jj = 0; jj < 4; jj++) {
                    int j = q * 4 + jj;
                    v0p[jj] = prmt(u[2*j], u[2*j+1], 0x5410);
                    v1p[jj] = prmt(u[2*j], u[2*j+1], 0x7632);
                }
                *(uint4*)(smem + stq[0][q]) = v0;
                *(uint4*)(smem + stq[1][q]) = v1;
            }
        }
        __syncthreads();
    }
}

// -------- launch --------
extern "C" void kernel_launch(void* const* d_in, const int* in_sizes, int n_in,
                              void* d_out, int out_size) {
    const float* x      = (const float*)d_in[0];
    const float* dw_w   = (const float*)d_in[1];
    const float* gamma1 = (const float*)d_in[2];
    const float* beta1  = (const float*)d_in[3];
    const float* mean1  = (const float*)d_in[4];
    const float* var1   = (const float*)d_in[5];
    const float* pw_w   = (const float*)d_in[6];
    const float* gamma2 = (const float*)d_in[7];
    const float* beta2  = (const float*)d_in[8];
    const float* mean2  = (const float*)d_in[9];
    const float* var2   = (const float*)d_in[10];
    float* out = (float*)d_out;

    cudaFuncSetAttribute(pw_kernel, cudaFuncAttributeMaxDynamicSharedMemorySize, 81920);

    init_kernel<<<(BB * HID * HWSZ + 511) / 512, 512>>>();
    prep_kernel<<<1, 256>>>(dw_w, gamma1, beta1, mean1, var1,
                            pw_w, gamma2, beta2, mean2, var2);

    for (int t = 0; t < TT; t++) {
        const float* hprev = (t == 0) ? (const float*)g_h0 : (const float*)out;
        dw_kernel<<<4096, 256>>>(x, hprev, t);
        pw_kernel<<<296, 256, 81920>>>(out, t);
    }
}

// round 15
// speedup vs baseline: 1.0051x; 1.0010x over previous
#include <cuda_runtime.h>
#include <cuda_bf16.h>
#include <cuda_fp16.h>
#include <cstdint>

// Problem constants
#define BB 8
#define TT 20
#define CIN 64
#define HID 64
#define HH 64
#define WW 64
#define HWSZ 4096          // 64*64
#define CC 128             // CIN + HID
#define C4 256             // 4*HID
#define EPSBN 1e-5f

typedef unsigned long long ull;

// -------- persistent device state --------
__device__ float g_h0[BB * HID * HWSZ];         // zero h for t=0
__device__ float g_c[BB * HID * HWSZ];
__device__ uint32_t g_d16[BB * CC * HWSZ / 2];  // fp16x2 selu(bn1(dw(z))), [b][k][px/2]
__device__ unsigned short g_wh[32768];          // fp16 W [r][k], swizzled (64KB)
__device__ float g_sp[256];                     // bn2 shift, [j*4+gate]
__device__ float g_dwf[CC * 9];
__device__ float g_dwb[CC];

// -------- helpers --------
__device__ __forceinline__ uint32_t smem_u32(const void* p) {
    uint32_t a;
    asm("{ .reg .u64 t; cvta.to.shared.u64 t, %1; cvt.u32.u64 %0, t; }" : "=r"(a) : "l"(p));
    return a;
}
__device__ __forceinline__ void ldm4(uint32_t* r, uint32_t a) {
    asm volatile("ldmatrix.sync.aligned.m8n8.x4.shared.b16 {%0,%1,%2,%3}, [%4];"
        : "=r"(r[0]), "=r"(r[1]), "=r"(r[2]), "=r"(r[3]) : "r"(a));
}
__device__ __forceinline__ void mma_f16(float* d, const uint32_t* a, uint32_t b0, uint32_t b1) {
    asm volatile("mma.sync.aligned.m16n8k16.row.col.f32.f16.f16.f32 "
        "{%0,%1,%2,%3}, {%4,%5,%6,%7}, {%8,%9}, {%0,%1,%2,%3};"
        : "+f"(d[0]), "+f"(d[1]), "+f"(d[2]), "+f"(d[3])
        : "r"(a[0]), "r"(a[1]), "r"(a[2]), "r"(a[3]), "r"(b0), "r"(b1));
}
__device__ __forceinline__ uint32_t prmt(uint32_t a, uint32_t b, uint32_t sel) {
    uint32_t r;
    asm("prmt.b32 %0, %1, %2, %3;" : "=r"(r) : "r"(a), "r"(b), "r"(sel));
    return r;
}
__device__ __forceinline__ float tanha(float x) {
    float r;
    asm("tanh.approx.f32 %0, %1;" : "=f"(r) : "f"(x));
    return r;
}
__device__ __forceinline__ float selu_f(float x) {
    const float s = 1.0507009873554805f;
    const float sa = 1.7580993408473766f;
    return x > 0.f ? s * x : sa * (__expf(x) - 1.f);
}
__device__ __forceinline__ float gate_f(float x) {       // exact: i, f, g
    float u = selu_f(x);
    return __fdividef(1.f, 1.f + __expf(-u));
}
__device__ __forceinline__ float gate_fast(float x) {    // o gate
    float u = selu_f(x);
    return 0.5f + 0.5f * tanha(0.5f * u);
}

// -------- init --------
__global__ void init_kernel() {
    int i = blockIdx.x * blockDim.x + threadIdx.x;
    if (i < BB * HID * HWSZ) { g_h0[i] = 0.f; g_c[i] = 0.f; }
}

// -------- prep --------
__global__ void prep_kernel(const float* __restrict__ dw_w,
                            const float* __restrict__ g1, const float* __restrict__ b1,
                            const float* __restrict__ m1, const float* __restrict__ v1,
                            const float* __restrict__ pw,
                            const float* __restrict__ g2, const float* __restrict__ b2,
                            const float* __restrict__ m2, const float* __restrict__ v2) {
    int tid = threadIdx.x;   // 256
    if (tid < CC) {
        float s = g1[tid] * rsqrtf(v1[tid] + EPSBN);
        #pragma unroll
        for (int k = 0; k < 9; k++) g_dwf[tid * 9 + k] = dw_w[tid * 9 + k] * s;
        g_dwb[tid] = b1[tid] - m1[tid] * s;
    }
    {
        int oc = tid;
        float s = g2[oc] * rsqrtf(v2[oc] + EPSBN);
        int gate = oc >> 6;
        int j = oc & 63;
        int r = j * 4 + gate;
        g_sp[r] = b2[oc] - m2[oc] * s;
        for (int k = 0; k < 128; k++) {
            float wv = pw[oc * 128 + k] * s;
            __half hw = __float2half(wv);
            uint32_t off = (uint32_t)r * 256 + (uint32_t)(((k >> 3) ^ (r & 7)) * 16) + (k & 7) * 2;
            g_wh[off >> 1] = *(unsigned short*)&hw;
        }
    }
}

// -------- depthwise 3x3 + BN1 + SELU -> fp16x2 --------
__global__ void dw_kernel(const float* __restrict__ x, const float* __restrict__ hprev, int t) {
    int idx = blockIdx.x * blockDim.x + threadIdx.x;   // 1,048,576 threads, 4 px each
    int w4 = idx & 15;
    int y  = (idx >> 4) & 63;
    int c  = (idx >> 10) & 127;
    int b  = idx >> 17;
    int x0 = w4 << 2;

    const float* src = (c < CIN)
        ? x + ((size_t)(b * TT + t) * CIN + c) * HWSZ
        : hprev + ((size_t)b * (size_t)(t == 0 ? HID : TT * HID) + (size_t)(t == 0 ? 0 : (t - 1) * HID) + (c - CIN)) * HWSZ;

    float r0[6], r1[6], r2[6];
    int ybase = y * WW;
    bool yt = (y > 0), yb = (y < HH - 1);
    #pragma unroll
    for (int dx = 0; dx < 6; dx++) {
        int xx = x0 - 1 + dx;
        bool xv = (xx >= 0) && (xx < WW);
        r0[dx] = (yt && xv) ? __ldg(src + ybase - WW + xx) : 0.f;
        r1[dx] = xv ? __ldg(src + ybase + xx) : 0.f;
        r2[dx] = (yb && xv) ? __ldg(src + ybase + WW + xx) : 0.f;
    }
    float w[9];
    #pragma unroll
    for (int i = 0; i < 9; i++) w[i] = __ldg(g_dwf + c * 9 + i);
    float bias = __ldg(g_dwb + c);

    float o[4];
    #pragma unroll
    for (int p = 0; p < 4; p++) {
        float acc = bias;
        acc += w[0]*r0[p] + w[1]*r0[p+1] + w[2]*r0[p+2];
        acc += w[3]*r1[p] + w[4]*r1[p+1] + w[5]*r1[p+2];
        acc += w[6]*r2[p] + w[7]*r2[p+1] + w[8]*r2[p+2];
        o[p] = selu_f(acc);
    }
    uint2 v;
    asm("cvt.rn.f16x2.f32 %0, %1, %2;" : "=r"(v.x) : "f"(o[1]), "f"(o[0]));
    asm("cvt.rn.f16x2.f32 %0, %1, %2;" : "=r"(v.y) : "f"(o[3]), "f"(o[2]));
    *(uint2*)(g_d16 + (((size_t)(b * CC + c) * HWSZ + ybase + x0) >> 1)) = v;
}

// -------- fp16 HMMA pointwise GEMM + LSTM epilogue --------
// 296 CTAs x 256 threads, 2 CTAs/SM for cross-CTA phase overlap.
// Tile = (b, 64 px) x 256 oc x 128 k; 512 tiles; CTA does tiles bid, bid+296.
// smem: W fp16 [0,64K), A fp16 [64K,80K) (64 rows x 256B).
__global__ void __launch_bounds__(256, 2)
pw_kernel(float* __restrict__ out, int t) {
    extern __shared__ char smem[];
    uint32_t sb = smem_u32(smem);
    int tid = threadIdx.x;
    int w = tid >> 5, lane = tid & 31;
    int pb = w & 1, ob = w >> 1;           // warp-tile: 32px x 64oc

    // stage W once (64 KB)
    {
        const float4* src = (const float4*)g_wh;
        float4* dst = (float4*)smem;
        #pragma unroll
        for (int i = 0; i < 16; i++) dst[tid + i * 256] = src[tid + i * 256];
    }

    // preload BN2 shifts
    float2 spr[8];
    #pragma unroll
    for (int nt = 0; nt < 8; nt++)
        spr[nt] = __ldg((const float2*)(g_sp + ob * 64 + nt * 8 + 2 * (lane & 3)));

    const uint32_t ABASE = sb + 65536;
    int arow = pb * 32 + (lane & 15);
    int apar = (lane >> 4) & 1;
    int asw  = arow & 7;
    int wrow = ob * 64 + (lane & 7) + (((lane >> 4) & 1) << 3);
    int wpar = (lane >> 3) & 1;
    int wsw  = wrow & 7;

    // A-build mapping: warp w owns kq = w (k-range w*16..w*16+15), lanes = px-pairs
    int kq = w;            // 0..7
    int p2 = lane;         // 0..31 -> px pair (2*p2, 2*p2+1)
    int px0 = 2 * p2, px1 = px0 + 1;
    uint32_t stq[2][2];    // [px][q] STS addresses
    #pragma unroll
    for (int q = 0; q < 2; q++) {
        stq[0][q] = 65536u + (uint32_t)px0 * 256 + (uint32_t)(((kq << 1) + q) ^ (px0 & 7)) * 16;
        stq[1][q] = 65536u + (uint32_t)px1 * 256 + (uint32_t)(((kq << 1) + q) ^ (px1 & 7)) * 16;
    }

    // prologue: build A for first tile
    {
        int tile = blockIdx.x;
        int b  = tile >> 6;
        int p0 = (tile & 63) << 6;
        const uint32_t* src = g_d16 + (((size_t)(b * CC + kq * 16) * HWSZ) >> 1) + (p0 >> 1) + p2;
        uint32_t u[16];
        #pragma unroll
        for (int i = 0; i < 16; i++) u[i] = __ldg(src + i * (HWSZ / 2));
        #pragma unroll
        for (int q = 0; q < 2; q++) {
            uint4 v0, v1;
            uint32_t* v0p = &v0.x; uint32_t* v1p = &v1.x;
            #pragma unroll
            for (int jj = 0; jj < 4; jj++) {
                int j = q * 4 + jj;
                v0p[jj] = prmt(u[2*j], u[2*j+1], 0x5410);
                v1p[jj] = prmt(u[2*j], u[2*j+1], 0x7632);
            }
            *(uint4*)(smem + stq[0][q]) = v0;
            *(uint4*)(smem + stq[1][q]) = v1;
        }
    }
    __syncthreads();

    for (int tile = blockIdx.x; tile < 512; tile += 296) {
        int b  = tile >> 6;
        int p0 = (tile & 63) << 6;
        int ntile = tile + 296;
        bool hasNext = ntile < 512;
        int nb  = ntile >> 6;
        int np0 = (ntile & 63) << 6;

        // ---- MMA mainloop ----
        float acc[2][8][4];
        #pragma unroll
        for (int mt = 0; mt < 2; mt++)
            #pragma unroll
            for (int nt = 0; nt < 8; nt++)
                #pragma unroll
                for (int q = 0; q < 4; q++) acc[mt][nt][q] = 0.f;

        #pragma unroll
        for (int kc = 0; kc < 8; kc++) {
            uint32_t ah[2][4];
            uint32_t chunkA = (uint32_t)((2 * kc + apar) ^ asw) * 16;
            ldm4(ah[0], ABASE + (uint32_t)arow * 256 + chunkA);
            ldm4(ah[1], ABASE + (uint32_t)(arow + 16) * 256 + chunkA);
            #pragma unroll
            for (int np = 0; np < 4; np++) {
                uint32_t chunk = (uint32_t)((2 * kc + wpar) ^ wsw);
                uint32_t addr = sb + (uint32_t)(wrow + np * 16) * 256 + chunk * 16;
                uint32_t wf[4];
                ldm4(wf, addr);
                #pragma unroll
                for (int mt = 0; mt < 2; mt++) {
                    mma_f16(acc[mt][np*2],   ah[mt], wf[0], wf[1]);
                    mma_f16(acc[mt][np*2+1], ah[mt], wf[2], wf[3]);
                }
            }
        }
        __syncthreads();

        // ---- prefetch next tile's A (latency hidden under epilogue) ----
        uint32_t u[16];
        if (hasNext) {
            const uint32_t* src = g_d16 + (((size_t)(nb * CC + kq * 16) * HWSZ) >> 1) + (np0 >> 1) + p2;
            #pragma unroll
            for (int i = 0; i < 16; i++) u[i] = __ldg(src + i * (HWSZ / 2));
        }

        // ---- epilogue ----
        int odd = lane & 1;
        #pragma unroll
        for (int uu = 0; uu < 16; uu++) {
            int mt = uu >> 3, nt = uu & 7;
            float* a = acc[mt][nt];
            float2 sp = spr[nt];
            float v0 = a[0] + sp.x, v1 = a[1] + sp.y;
            float v2 = a[2] + sp.x, v3 = a[3] + sp.y;
            float sx = odd ? v0 : v2;
            float sy = odd ? v1 : v3;
            float ex = __shfl_xor_sync(0xFFFFFFFFu, sx, 1);
            float ey = __shfl_xor_sync(0xFFFFFFFFu, sy, 1);
            float zi, zf, zo, zg; int rr;
            if (!odd) { zi = v0; zf = v1; zo = ex; zg = ey; rr = lane >> 2; }
            else      { zi = ex; zf = ey; zo = v2; zg = v3; rr = (lane >> 2) + 8; }
            int j   = ob * 16 + nt * 2 + ((lane >> 1) & 1);
            int ppx = pb * 32 + mt * 16 + rr;
            size_t plane = ((size_t)b * HID + j) * HWSZ + p0 + ppx;
            float co = __ldg(g_c + plane);
            float gi = gate_f(zi);
            float gf = gate_f(zf);
            float gg = gate_f(zg);
            float go = gate_fast(zo);
            float cv = gf * co + gi * gg;
            float hv = go * tanha(cv);
            g_c[plane] = cv;
            out[((size_t)(b * TT + t) * HID + j) * HWSZ + p0 + ppx] = hv;
        }

        // ---- store next tile's A ----
        if (hasNext) {
            #pragma unroll
            for (int q = 0; q < 2; q++) {
                uint4 v0, v1;
                uint32_t* v0p = &v0.x; uint32_t* v1p = &v1.x;
                #pragma unroll
                for (int jj = 0; jj < 4; jj++) {
                    int j = q * 4 + jj;
                    v0p[jj] = prmt(u[2*j], u[2*j+1], 0x5410);
                    v1p[jj] = prmt(u[2*j], u[2*j+1], 0x7632);
                }
                *(uint4*)(smem + stq[0][q]) = v0;
                *(uint4*)(smem + stq[1][q]) = v1;
            }
        }
        __syncthreads();
    }
}

// -------- launch --------
extern "C" void kernel_launch(void* const* d_in, const int* in_sizes, int n_in,
                              void* d_out, int out_size) {
    const float* x      = (const float*)d_in[0];
    const float* dw_w   = (const float*)d_in[1];
    const float* gamma1 = (const float*)d_in[2];
    const float* beta1  = (const float*)d_in[3];
    const float* mean1  = (const float*)d_in[4];
    const float* var1   = (const float*)d_in[5];
    const float* pw_w   = (const float*)d_in[6];
    const float* gamma2 = (const float*)d_in[7];
    const float* beta2  = (const float*)d_in[8];
    const float* mean2  = (const float*)d_in[9];
    const float* var2   = (const float*)d_in[10];
    float* out = (float*)d_out;

    cudaFuncSetAttribute(pw_kernel, cudaFuncAttributeMaxDynamicSharedMemorySize, 81920);

    init_kernel<<<(BB * HID * HWSZ + 511) / 512, 512>>>();
    prep_kernel<<<1, 256>>>(dw_w, gamma1, beta1, mean1, var1,
                            pw_w, gamma2, beta2, mean2, var2);

    for (int t = 0; t < TT; t++) {
        const float* hprev = (t == 0) ? (const float*)g_h0 : (const float*)out;
        dw_kernel<<<4096, 256>>>(x, hprev, t);
        pw_kernel<<<296, 256, 81920>>>(out, t);
    }
}